// round 7
// baseline (speedup 1.0000x reference)
#include <cuda_runtime.h>
#include <cuda_bf16.h>
#include <cstdint>

// Problem constants
#define Bb 2
#define Tt 2048
#define Cc 1280
#define Hh 10
#define Dd 128
#define Mtot (Bb*Tt)          // 4096
#define WSZ (Cc*Cc)           // one weight matrix
#define SOFT_SCALE 0.08838834764831845f  // 1/sqrt(128)

// Scratch (device globals; allocation-free rule)
__device__ float g_q[Bb*Hh*Tt*Dd];
__device__ float g_k[Bb*Hh*Tt*Dd];
__device__ float g_v[Bb*Hh*Tt*Dd];
// bf16 split operands (hi/lo), packed as uint32 pairs / bf16 element arrays
__device__ uint32_t g_xh[Mtot*Cc/2],  g_xl[Mtot*Cc/2];   // x split
__device__ uint32_t g_wh[4*WSZ/2],    g_wl[4*WSZ/2];     // Wq,Wk,Wv,Wproj split
__device__ uint32_t g_ath[Mtot*Cc/2], g_atl[Mtot*Cc/2];  // attention out split

// ---------------------------------------------------------------------------
// Helpers
// ---------------------------------------------------------------------------
__device__ __forceinline__ void cvt_split_pair(float x, float y,
                                               uint32_t& hi, uint32_t& lo) {
    __nv_bfloat16 hx = __float2bfloat16_rn(x);
    __nv_bfloat16 hy = __float2bfloat16_rn(y);
    __nv_bfloat16 lx = __float2bfloat16_rn(x - __bfloat162float(hx));
    __nv_bfloat16 ly = __float2bfloat16_rn(y - __bfloat162float(hy));
    __nv_bfloat162 h; h.x = hx; h.y = hy;
    __nv_bfloat162 l; l.x = lx; l.y = ly;
    hi = *reinterpret_cast<uint32_t*>(&h);
    lo = *reinterpret_cast<uint32_t*>(&l);
}

#define BF16_MMA(d, a, b) \
    asm volatile( \
        "mma.sync.aligned.m16n8k16.row.col.f32.bf16.bf16.f32 " \
        "{%0,%1,%2,%3}, {%4,%5,%6,%7}, {%8,%9}, {%0,%1,%2,%3};\n" \
        : "+f"(d[0]), "+f"(d[1]), "+f"(d[2]), "+f"(d[3]) \
        : "r"(a[0]), "r"(a[1]), "r"(a[2]), "r"(a[3]), "r"(b[0]), "r"(b[1]))

#define LDSM4(r0, r1, r2, r3, addr) \
    asm volatile("ldmatrix.sync.aligned.m8n8.x4.shared.b16 {%0,%1,%2,%3}, [%4];" \
        : "=r"(r0), "=r"(r1), "=r"(r2), "=r"(r3) : "r"(addr))

#define CP_ASYNC16(dst, src) \
    asm volatile("cp.async.cg.shared.global [%0], [%1], 16;" \
        :: "r"(dst), "l"(src))
#define CP_COMMIT() asm volatile("cp.async.commit_group;" ::: "memory")
#define CP_WAIT(n)  asm volatile("cp.async.wait_group %0;" :: "n"(n) : "memory")

__device__ __forceinline__ uint32_t s2u(const void* p) {
    uint32_t a;
    asm("{ .reg .u64 t; cvta.to.shared.u64 t, %1; cvt.u32.u64 %0, t; }"
        : "=r"(a) : "l"(p));
    return a;
}

// ---------------------------------------------------------------------------
// Elementwise fp32 -> bf16 hi/lo split (pre-pass for GEMM operands)
// ---------------------------------------------------------------------------
__global__ __launch_bounds__(256) void split_kernel(
    const float* __restrict__ src, uint32_t* __restrict__ dh,
    uint32_t* __restrict__ dl, int n4)
{
    int i = blockIdx.x * 256 + threadIdx.x;
    if (i >= n4) return;
    float4 v = *(const float4*)(src + 4 * (long)i);
    uint32_t h0, l0, h1, l1;
    cvt_split_pair(v.x, v.y, h0, l0);
    cvt_split_pair(v.z, v.w, h1, l1);
    dh[2 * i] = h0; dh[2 * i + 1] = h1;
    dl[2 * i] = l0; dl[2 * i + 1] = l1;
}

// ---------------------------------------------------------------------------
// bf16 split-3 GEMM, mma.sync + ldmatrix + cp.async:
//   Out[m,n] = sum_k A[m,k] * W[n,k], near-fp32 via Ah*Bh + Ah*Bl + Al*Bh.
// Block 128x128, BK=32 bf16 (64B rows, stride 80B -> conflict-free ldmatrix),
// double-buffered cp.async stages, 8 warps (2m x 4n), warp tile 64x32.
// mode 0: A = att split, write Out (proj). mode 1: z picks W -> g_q/g_k/g_v.
// ---------------------------------------------------------------------------
#define STRB 80                 // smem row stride bytes (32 bf16 + 8 pad)
#define OFF_AH 0
#define OFF_AL (128*STRB)
#define OFF_BH (2*128*STRB)
#define OFF_BL (3*128*STRB)
#define STAGE_B (4*128*STRB)    // 40960
#define GEMM_SMEM (2*STAGE_B)   // 81920

__global__ __launch_bounds__(256, 2) void gemm_split(
    const uint32_t* __restrict__ Ah_u,
    const uint32_t* __restrict__ Al_u,
    float* __restrict__ Out,
    int mode)
{
    extern __shared__ char smc[];
    const uint32_t sb = s2u(smc);

    const int tid  = threadIdx.x;
    const int warp = tid >> 5;
    const int lane = tid & 31;
    const int wm = warp & 1;
    const int wn = warp >> 1;
    const int gid = lane >> 2;
    const int tig = lane & 3;

    const int m0 = blockIdx.y * 128;
    const int n0 = blockIdx.x * 128;
    const int z  = (mode == 0) ? 3 : blockIdx.z;

    const __nv_bfloat16* Ah_g = (const __nv_bfloat16*)Ah_u;
    const __nv_bfloat16* Al_g = (const __nv_bfloat16*)Al_u;
    const __nv_bfloat16* Wh_g = (const __nv_bfloat16*)(g_wh) + (long)z * WSZ;
    const __nv_bfloat16* Wl_g = (const __nv_bfloat16*)(g_wl) + (long)z * WSZ;
    float* O = (mode == 0) ? Out : ((z == 0) ? g_q : ((z == 1) ? g_k : g_v));

    // cp.async mapping: per matrix 512 chunks of 16B (128 rows x 4), 2/thread
    const int ch0_row = tid >> 2,          ch0_kc = tid & 3;
    const int ch1_row = (tid + 256) >> 2,  ch1_kc = tid & 3;

    float acc[4][4][4];
#pragma unroll
    for (int mi = 0; mi < 4; mi++)
#pragma unroll
        for (int ni = 0; ni < 4; ni++)
#pragma unroll
            for (int c = 0; c < 4; c++) acc[mi][ni][c] = 0.f;

    const int NCH = Cc / 32;   // 40 stages

    // ldmatrix base addresses (per thread)
    const uint32_t aRow = wm * 64 + (lane & 7) + ((lane >> 3) & 1) * 8;
    const uint32_t aOff = aRow * STRB + (lane >> 4) * 16;
    const uint32_t bRow = wn * 32 + (lane & 7) + ((lane >> 4) << 3);
    const uint32_t bOff = bRow * STRB + ((lane >> 3) & 1) * 16;

    auto issue_stage = [&](int stage, int buf) {
        const int kc0 = stage * 32;
        const uint32_t stB = sb + buf * STAGE_B;
        {
            uint32_t so = ch0_row * STRB + ch0_kc * 16;
            long ga = (long)(m0 + ch0_row) * Cc + kc0 + ch0_kc * 8;
            long gb = (long)(n0 + ch0_row) * Cc + kc0 + ch0_kc * 8;
            CP_ASYNC16(stB + OFF_AH + so, Ah_g + ga);
            CP_ASYNC16(stB + OFF_AL + so, Al_g + ga);
            CP_ASYNC16(stB + OFF_BH + so, Wh_g + gb);
            CP_ASYNC16(stB + OFF_BL + so, Wl_g + gb);
        }
        {
            uint32_t so = ch1_row * STRB + ch1_kc * 16;
            long ga = (long)(m0 + ch1_row) * Cc + kc0 + ch1_kc * 8;
            long gb = (long)(n0 + ch1_row) * Cc + kc0 + ch1_kc * 8;
            CP_ASYNC16(stB + OFF_AH + so, Ah_g + ga);
            CP_ASYNC16(stB + OFF_AL + so, Al_g + ga);
            CP_ASYNC16(stB + OFF_BH + so, Wh_g + gb);
            CP_ASYNC16(stB + OFF_BL + so, Wl_g + gb);
        }
        CP_COMMIT();
    };

    issue_stage(0, 0);

    for (int c = 0; c < NCH; c++) {
        const int buf = c & 1;
        if (c + 1 < NCH) {
            issue_stage(c + 1, buf ^ 1);
            CP_WAIT(1);
        } else {
            CP_WAIT(0);
        }
        __syncthreads();

        const uint32_t base = sb + buf * STAGE_B;
#pragma unroll
        for (int kk = 0; kk < 2; kk++) {
            const uint32_t ko = kk * 32;
            uint32_t bh[4][2], bl[4][2];
#pragma unroll
            for (int p = 0; p < 2; p++) {
                uint32_t t0, t1, t2, t3;
                LDSM4(t0, t1, t2, t3, base + OFF_BH + bOff + p * (16 * STRB) + ko);
                bh[2 * p][0] = t0; bh[2 * p][1] = t1;
                bh[2 * p + 1][0] = t2; bh[2 * p + 1][1] = t3;
                LDSM4(t0, t1, t2, t3, base + OFF_BL + bOff + p * (16 * STRB) + ko);
                bl[2 * p][0] = t0; bl[2 * p][1] = t1;
                bl[2 * p + 1][0] = t2; bl[2 * p + 1][1] = t3;
            }
#pragma unroll
            for (int mi = 0; mi < 4; mi++) {
                uint32_t ah[4], al[4];
                LDSM4(ah[0], ah[1], ah[2], ah[3],
                      base + OFF_AH + aOff + mi * (16 * STRB) + ko);
                LDSM4(al[0], al[1], al[2], al[3],
                      base + OFF_AL + aOff + mi * (16 * STRB) + ko);
#pragma unroll
                for (int ni = 0; ni < 4; ni++) {
                    BF16_MMA(acc[mi][ni], ah, bh[ni]);
                    BF16_MMA(acc[mi][ni], ah, bl[ni]);
                    BF16_MMA(acc[mi][ni], al, bh[ni]);
                }
            }
        }
        __syncthreads();
    }

    // Epilogue (verified R3 fragment mapping)
#pragma unroll
    for (int mi = 0; mi < 4; mi++) {
#pragma unroll
        for (int ni = 0; ni < 4; ni++) {
            int r_lo = m0 + wm * 64 + mi * 16 + gid;
            int cn = n0 + wn * 32 + ni * 8 + 2 * tig;
            float2 lo = make_float2(acc[mi][ni][0], acc[mi][ni][1]);
            float2 hi = make_float2(acc[mi][ni][2], acc[mi][ni][3]);
            if (mode == 0) {
                *(float2*)(O + (long)r_lo * Cc + cn)       = lo;
                *(float2*)(O + (long)(r_lo + 8) * Cc + cn) = hi;
            } else {
                int h_ = n0 >> 7;
                int d_ = cn - n0;
                int b0_ = r_lo >> 11, t0_ = r_lo & (Tt - 1);
                int b1_ = (r_lo + 8) >> 11, t1_ = (r_lo + 8) & (Tt - 1);
                long base0 = ((long)(b0_ * Hh + h_) * Tt + t0_) * Dd + d_;
                long base1 = ((long)(b1_ * Hh + h_) * Tt + t1_) * Dd + d_;
                *(float2*)(O + base0) = lo;
                *(float2*)(O + base1) = hi;
            }
        }
    }
}

// ---------------------------------------------------------------------------
// Fused RoPE + RMSNorm on g_q / g_k, one warp per (b,h,t) row of 128.
// ---------------------------------------------------------------------------
__global__ __launch_bounds__(256) void rope_rms_kernel(
    const float* __restrict__ cosp, const float* __restrict__ sinp)
{
    int warp = threadIdx.x >> 5;
    int lane = threadIdx.x & 31;
    int row = blockIdx.x * 8 + warp;
    float* buf = (blockIdx.y == 0) ? g_q : g_k;
    int t = row & (Tt - 1);
    float* p = buf + (long)row * Dd;

    float x0 = p[lane], x1 = p[lane + 32], x2 = p[lane + 64], x3 = p[lane + 96];
    float c0 = cosp[t * 64 + lane], c1 = cosp[t * 64 + lane + 32];
    float s0 = sinp[t * 64 + lane], s1 = sinp[t * 64 + lane + 32];

    float y0 =  x0 * c0 + x2 * s0;
    float y2 = -x0 * s0 + x2 * c0;
    float y1 =  x1 * c1 + x3 * s1;
    float y3 = -x1 * s1 + x3 * c1;

    float ss = y0 * y0 + y1 * y1 + y2 * y2 + y3 * y3;
#pragma unroll
    for (int o = 16; o; o >>= 1) ss += __shfl_xor_sync(0xFFFFFFFFu, ss, o);
    float inv = rsqrtf(ss * (1.0f / 128.0f) + 1e-5f);

    p[lane]      = y0 * inv;
    p[lane + 32] = y1 * inv;
    p[lane + 64] = y2 * inv;
    p[lane + 96] = y3 * inv;
}

// ---------------------------------------------------------------------------
// Flash attention, bf16 split-3 mma.sync (R5-proven). Epilogue now writes the
// attention output directly as split bf16 (feeds proj GEMM; no fp32 pass).
// ---------------------------------------------------------------------------
#define FQP 68
#define FKP 68
#define FVP 36
#define FLASH_SMEM_BYTES ((2*128*FQP + 2*64*FKP + 2*128*FVP) * 4)

__global__ __launch_bounds__(256) void flash_mma_kernel()
{
    extern __shared__ uint32_t smu[];
    uint32_t* Qh = smu;
    uint32_t* Ql = Qh + 128 * FQP;
    uint32_t* Kh = Ql + 128 * FQP;
    uint32_t* Kl = Kh + 64 * FKP;
    uint32_t* Vh = Kl + 64 * FKP;
    uint32_t* Vl = Vh + 128 * FVP;

    const int tid  = threadIdx.x;
    const int wid  = tid >> 5;
    const int lane = tid & 31;
    const int gid  = lane >> 2;
    const int tig  = lane & 3;

    const int qtile = gridDim.x - 1 - blockIdx.x;
    const int bh = blockIdx.y;
    const int b_ = bh / Hh, h_ = bh % Hh;
    const long base = (long)bh * Tt * Dd;
    const float* qb = g_q + base;
    const float* kb = g_k + base;
    const float* vb = g_v + base;
    const int qb0 = qtile * 128;

    for (int i = tid; i < 128 * 32; i += 256) {
        int r = i >> 5, f4 = i & 31;
        float4 v = *(const float4*)(qb + (long)(qb0 + r) * Dd + f4 * 4);
        uint32_t h0, l0, h1, l1;
        cvt_split_pair(v.x * SOFT_SCALE, v.y * SOFT_SCALE, h0, l0);
        cvt_split_pair(v.z * SOFT_SCALE, v.w * SOFT_SCALE, h1, l1);
        Qh[r * FQP + 2 * f4]     = h0; Qh[r * FQP + 2 * f4 + 1] = h1;
        Ql[r * FQP + 2 * f4]     = l0; Ql[r * FQP + 2 * f4 + 1] = l1;
    }

    float o[16][4];
    float m_[2], l_[2];
#pragma unroll
    for (int ni = 0; ni < 16; ni++)
#pragma unroll
        for (int c = 0; c < 4; c++) o[ni][c] = 0.f;
    m_[0] = m_[1] = -1e30f;
    l_[0] = l_[1] = 0.f;

    const int qrow = wid * 16;
    const int ktmax = 2 * qtile + 2;

    for (int kt = 0; kt < ktmax; kt++) {
        __syncthreads();
        const int kbase = kt * 64;

        for (int i = tid; i < 64 * 32; i += 256) {
            int r = i >> 5, f4 = i & 31;
            float4 v = *(const float4*)(kb + (long)(kbase + r) * Dd + f4 * 4);
            uint32_t h0, l0, h1, l1;
            cvt_split_pair(v.x, v.y, h0, l0);
            cvt_split_pair(v.z, v.w, h1, l1);
            Kh[r * FKP + 2 * f4]     = h0; Kh[r * FKP + 2 * f4 + 1] = h1;
            Kl[r * FKP + 2 * f4]     = l0; Kl[r * FKP + 2 * f4 + 1] = l1;
        }
        for (int i = tid; i < 128 * 32; i += 256) {
            int d = i & 127, kp = i >> 7;
            float v0 = vb[(long)(kbase + 2 * kp) * Dd + d];
            float v1 = vb[(long)(kbase + 2 * kp + 1) * Dd + d];
            uint32_t h, l;
            cvt_split_pair(v0, v1, h, l);
            Vh[d * FVP + kp] = h;
            Vl[d * FVP + kp] = l;
        }
        __syncthreads();

        float s[8][4];
#pragma unroll
        for (int t = 0; t < 8; t++)
#pragma unroll
            for (int c = 0; c < 4; c++) s[t][c] = 0.f;

#pragma unroll
        for (int j = 0; j < 8; j++) {
            uint32_t ah[4], al[4];
            ah[0] = Qh[(qrow + gid) * FQP + 8 * j + tig];
            ah[1] = Qh[(qrow + gid + 8) * FQP + 8 * j + tig];
            ah[2] = Qh[(qrow + gid) * FQP + 8 * j + tig + 4];
            ah[3] = Qh[(qrow + gid + 8) * FQP + 8 * j + tig + 4];
            al[0] = Ql[(qrow + gid) * FQP + 8 * j + tig];
            al[1] = Ql[(qrow + gid + 8) * FQP + 8 * j + tig];
            al[2] = Ql[(qrow + gid) * FQP + 8 * j + tig + 4];
            al[3] = Ql[(qrow + gid + 8) * FQP + 8 * j + tig + 4];
#pragma unroll
            for (int ni = 0; ni < 8; ni++) {
                uint32_t bh2[2], bl2[2];
                bh2[0] = Kh[(8 * ni + gid) * FKP + 8 * j + tig];
                bh2[1] = Kh[(8 * ni + gid) * FKP + 8 * j + tig + 4];
                bl2[0] = Kl[(8 * ni + gid) * FKP + 8 * j + tig];
                bl2[1] = Kl[(8 * ni + gid) * FKP + 8 * j + tig + 4];
                BF16_MMA(s[ni], ah, bh2);
                BF16_MMA(s[ni], ah, bl2);
                BF16_MMA(s[ni], al, bh2);
            }
        }

        if (kt >= 2 * qtile) {
            int r0g = qb0 + qrow + gid;
#pragma unroll
            for (int t = 0; t < 8; t++) {
                int col = kbase + 8 * t + 2 * tig;
                if (col     > r0g)     s[t][0] = -1e30f;
                if (col + 1 > r0g)     s[t][1] = -1e30f;
                if (col     > r0g + 8) s[t][2] = -1e30f;
                if (col + 1 > r0g + 8) s[t][3] = -1e30f;
            }
        }

#pragma unroll
        for (int r = 0; r < 2; r++) {
            float mx = -1e30f;
#pragma unroll
            for (int t = 0; t < 8; t++)
                mx = fmaxf(mx, fmaxf(s[t][2 * r], s[t][2 * r + 1]));
            mx = fmaxf(mx, __shfl_xor_sync(0xFFFFFFFFu, mx, 1));
            mx = fmaxf(mx, __shfl_xor_sync(0xFFFFFFFFu, mx, 2));
            float mn = fmaxf(m_[r], mx);
            float alpha = __expf(m_[r] - mn);
            float sum = 0.f;
#pragma unroll
            for (int t = 0; t < 8; t++) {
                float p0 = __expf(s[t][2 * r]     - mn);
                float p1 = __expf(s[t][2 * r + 1] - mn);
                s[t][2 * r] = p0; s[t][2 * r + 1] = p1;
                sum += p0 + p1;
            }
            sum += __shfl_xor_sync(0xFFFFFFFFu, sum, 1);
            sum += __shfl_xor_sync(0xFFFFFFFFu, sum, 2);
            l_[r] = l_[r] * alpha + sum;
            m_[r] = mn;
#pragma unroll
            for (int ni = 0; ni < 16; ni++) {
                o[ni][2 * r]     *= alpha;
                o[ni][2 * r + 1] *= alpha;
            }
        }

#pragma unroll
        for (int j = 0; j < 4; j++) {
            uint32_t ah[4], al[4];
            cvt_split_pair(s[2 * j][0],     s[2 * j][1],     ah[0], al[0]);
            cvt_split_pair(s[2 * j][2],     s[2 * j][3],     ah[1], al[1]);
            cvt_split_pair(s[2 * j + 1][0], s[2 * j + 1][1], ah[2], al[2]);
            cvt_split_pair(s[2 * j + 1][2], s[2 * j + 1][3], ah[3], al[3]);
#pragma unroll
            for (int ni = 0; ni < 16; ni++) {
                uint32_t bh2[2], bl2[2];
                bh2[0] = Vh[(8 * ni + gid) * FVP + 8 * j + tig];
                bh2[1] = Vh[(8 * ni + gid) * FVP + 8 * j + tig + 4];
                bl2[0] = Vl[(8 * ni + gid) * FVP + 8 * j + tig];
                bl2[1] = Vl[(8 * ni + gid) * FVP + 8 * j + tig + 4];
                BF16_MMA(o[ni], ah, bh2);
                BF16_MMA(o[ni], ah, bl2);
                BF16_MMA(o[ni], al, bh2);
            }
        }
    }

    // Epilogue: normalize, split to bf16 hi/lo, write g_ath/g_atl directly.
    float inv0 = 1.f / l_[0];
    float inv1 = 1.f / l_[1];
    int r0g = qb0 + qrow + gid;
    long pb0 = (((long)(b_ * Tt + r0g))     * Cc + h_ * Dd) >> 1;
    long pb1 = (((long)(b_ * Tt + r0g + 8)) * Cc + h_ * Dd) >> 1;
#pragma unroll
    for (int ni = 0; ni < 16; ni++) {
        int dp = 4 * ni + tig;   // pair index within head
        uint32_t h, l;
        cvt_split_pair(o[ni][0] * inv0, o[ni][1] * inv0, h, l);
        g_ath[pb0 + dp] = h; g_atl[pb0 + dp] = l;
        cvt_split_pair(o[ni][2] * inv1, o[ni][3] * inv1, h, l);
        g_ath[pb1 + dp] = h; g_atl[pb1 + dp] = l;
    }
}

// ---------------------------------------------------------------------------
extern "C" void kernel_launch(void* const* d_in, const int* in_sizes, int n_in,
                              void* d_out, int out_size)
{
    const float* x    = (const float*)d_in[0];
    const float* cosp = (const float*)d_in[1];
    const float* sinp = (const float*)d_in[2];
    const float* Wq   = (const float*)d_in[3];
    const float* Wk   = (const float*)d_in[4];
    const float* Wv   = (const float*)d_in[5];
    const float* Wp   = (const float*)d_in[6];
    float* out = (float*)d_out;

    cudaFuncSetAttribute(gemm_split,
                         cudaFuncAttributeMaxDynamicSharedMemorySize, GEMM_SMEM);
    cudaFuncSetAttribute(flash_mma_kernel,
                         cudaFuncAttributeMaxDynamicSharedMemorySize,
                         FLASH_SMEM_BYTES);

    // Resolve device-global addresses host-side
    uint32_t *xh_p, *xl_p, *wh_p, *wl_p;
    cudaGetSymbolAddress((void**)&xh_p, g_xh);
    cudaGetSymbolAddress((void**)&xl_p, g_xl);
    cudaGetSymbolAddress((void**)&wh_p, g_wh);
    cudaGetSymbolAddress((void**)&wl_p, g_wl);
    uint32_t *ath_p, *atl_p;
    cudaGetSymbolAddress((void**)&ath_p, g_ath);
    cudaGetSymbolAddress((void**)&atl_p, g_atl);

    // 0) Split x and the four weight matrices into bf16 hi/lo
    const int xn4 = Mtot * Cc / 4;   // 1,310,720
    const int wn4 = WSZ / 4;         // 409,600
    split_kernel<<<(xn4 + 255) / 256, 256>>>(x, xh_p, xl_p, xn4);
    split_kernel<<<(wn4 + 255) / 256, 256>>>(Wq, wh_p + 0 * WSZ / 2, wl_p + 0 * WSZ / 2, wn4);
    split_kernel<<<(wn4 + 255) / 256, 256>>>(Wk, wh_p + 1 * WSZ / 2, wl_p + 1 * WSZ / 2, wn4);
    split_kernel<<<(wn4 + 255) / 256, 256>>>(Wv, wh_p + 2 * WSZ / 2, wl_p + 2 * WSZ / 2, wn4);
    split_kernel<<<(wn4 + 255) / 256, 256>>>(Wp, wh_p + 3 * WSZ / 2, wl_p + 3 * WSZ / 2, wn4);

    // 1) Q/K/V projections (bf16 split-3, ldmatrix + cp.async)
    gemm_split<<<dim3(Cc / 128, Mtot / 128, 3), 256, GEMM_SMEM>>>(xh_p, xl_p, nullptr, 1);
    // 2) RoPE + RMSNorm
    rope_rms_kernel<<<dim3((Bb * Hh * Tt) / 8, 2), 256>>>(cosp, sinp);
    // 3) Flash attention (writes split attention output)
    flash_mma_kernel<<<dim3(Tt / 128, Bb * Hh), 256, FLASH_SMEM_BYTES>>>();
    // 4) Output projection
    gemm_split<<<dim3(Cc / 128, Mtot / 128, 1), 256, GEMM_SMEM>>>(ath_p, atl_p, out, 0);
}

// round 8
// speedup vs baseline: 1.4893x; 1.4893x over previous
#include <cuda_runtime.h>
#include <cuda_bf16.h>
#include <cuda_fp16.h>
#include <cstdint>

// Problem constants
#define Bb 2
#define Tt 2048
#define Cc 1280
#define Hh 10
#define Dd 128
#define Mtot (Bb*Tt)          // 4096
#define WSZ (Cc*Cc)
#define SOFT_SCALE 0.08838834764831845f  // 1/sqrt(128)

// Scratch (device globals; allocation-free rule)
__device__ float g_q[Bb*Hh*Tt*Dd];
__device__ float g_k[Bb*Hh*Tt*Dd];
__device__ float g_v[Bb*Hh*Tt*Dd];
__device__ uint32_t g_xf[Mtot*Cc/2];     // x in fp16 (half2 packed)
__device__ uint32_t g_wf[4*WSZ/2];       // Wq,Wk,Wv,Wproj in fp16
__device__ uint32_t g_atf[Mtot*Cc/2];    // attention out in fp16 [b,t,h,d]

// ---------------------------------------------------------------------------
// Helpers
// ---------------------------------------------------------------------------
__device__ __forceinline__ void cvt_split_pair(float x, float y,
                                               uint32_t& hi, uint32_t& lo) {
    __nv_bfloat16 hx = __float2bfloat16_rn(x);
    __nv_bfloat16 hy = __float2bfloat16_rn(y);
    __nv_bfloat16 lx = __float2bfloat16_rn(x - __bfloat162float(hx));
    __nv_bfloat16 ly = __float2bfloat16_rn(y - __bfloat162float(hy));
    __nv_bfloat162 h; h.x = hx; h.y = hy;
    __nv_bfloat162 l; l.x = lx; l.y = ly;
    hi = *reinterpret_cast<uint32_t*>(&h);
    lo = *reinterpret_cast<uint32_t*>(&l);
}

#define BF16_MMA(d, a, b) \
    asm volatile( \
        "mma.sync.aligned.m16n8k16.row.col.f32.bf16.bf16.f32 " \
        "{%0,%1,%2,%3}, {%4,%5,%6,%7}, {%8,%9}, {%0,%1,%2,%3};\n" \
        : "+f"(d[0]), "+f"(d[1]), "+f"(d[2]), "+f"(d[3]) \
        : "r"(a[0]), "r"(a[1]), "r"(a[2]), "r"(a[3]), "r"(b[0]), "r"(b[1]))

#define F16_MMA(d, a, b) \
    asm volatile( \
        "mma.sync.aligned.m16n8k16.row.col.f32.f16.f16.f32 " \
        "{%0,%1,%2,%3}, {%4,%5,%6,%7}, {%8,%9}, {%0,%1,%2,%3};\n" \
        : "+f"(d[0]), "+f"(d[1]), "+f"(d[2]), "+f"(d[3]) \
        : "r"(a[0]), "r"(a[1]), "r"(a[2]), "r"(a[3]), "r"(b[0]), "r"(b[1]))

#define LDSM4(r0, r1, r2, r3, addr) \
    asm volatile("ldmatrix.sync.aligned.m8n8.x4.shared.b16 {%0,%1,%2,%3}, [%4];" \
        : "=r"(r0), "=r"(r1), "=r"(r2), "=r"(r3) : "r"(addr))

#define CP_ASYNC16(dst, src) \
    asm volatile("cp.async.cg.shared.global [%0], [%1], 16;" \
        :: "r"(dst), "l"(src))
#define CP_COMMIT() asm volatile("cp.async.commit_group;" ::: "memory")
#define CP_WAIT(n)  asm volatile("cp.async.wait_group %0;" :: "n"(n) : "memory")

__device__ __forceinline__ uint32_t s2u(const void* p) {
    uint32_t a;
    asm("{ .reg .u64 t; cvta.to.shared.u64 t, %1; cvt.u32.u64 %0, t; }"
        : "=r"(a) : "l"(p));
    return a;
}

// ---------------------------------------------------------------------------
// Elementwise fp32 -> fp16 convert (GEMM operand pre-pass)
// ---------------------------------------------------------------------------
__global__ __launch_bounds__(256) void cvt_f16_kernel(
    const float* __restrict__ src, uint32_t* __restrict__ dst, int n4)
{
    int i = blockIdx.x * 256 + threadIdx.x;
    if (i >= n4) return;
    float4 v = *(const float4*)(src + 4 * (long)i);
    __half2 p0 = __floats2half2_rn(v.x, v.y);
    __half2 p1 = __floats2half2_rn(v.z, v.w);
    dst[2 * i]     = *reinterpret_cast<uint32_t*>(&p0);
    dst[2 * i + 1] = *reinterpret_cast<uint32_t*>(&p1);
}

// ---------------------------------------------------------------------------
// fp16 single-pass GEMM (TF32-grade accuracy, bf16-rate tensor throughput):
//   Out[m,n] = sum_k A[m,k] * W[n,k]
// Block 128x128, BK=32 fp16 (64B rows, stride 80B), 4-stage cp.async pipeline
// (one commit per iteration -> wait_group 3 is exact), 8 warps (2m x 4n),
// warp tile 64x32, fragments via ldmatrix.x4 (addressing verified in R7).
// mode 0: A = g_atf, write Out (proj). mode 1: z picks W -> g_q/g_k/g_v.
// ---------------------------------------------------------------------------
#define STRB 80
#define OFF_A 0
#define OFF_B (128*STRB)
#define STAGE_B (2*128*STRB)      // 20480
#define NSTAGE 4
#define GEMM_SMEM (NSTAGE*STAGE_B)   // 81920

__global__ __launch_bounds__(256, 2) void gemm_f16(
    const uint32_t* __restrict__ A_u,
    float* __restrict__ Out,
    int mode)
{
    extern __shared__ char smc[];
    const uint32_t sb = s2u(smc);

    const int tid  = threadIdx.x;
    const int warp = tid >> 5;
    const int lane = tid & 31;
    const int wm = warp & 1;
    const int wn = warp >> 1;
    const int gid = lane >> 2;
    const int tig = lane & 3;

    const int m0 = blockIdx.y * 128;
    const int n0 = blockIdx.x * 128;
    const int z  = (mode == 0) ? 3 : blockIdx.z;

    const __half* A_g = (const __half*)A_u;
    const __half* W_g = (const __half*)(g_wf) + (long)z * WSZ;
    float* O = (mode == 0) ? Out : ((z == 0) ? g_q : ((z == 1) ? g_k : g_v));

    // cp.async: 512 16B chunks per matrix, 2 per thread per matrix
    const int ch0_row = tid >> 2,          ch0_kc = tid & 3;
    const int ch1_row = (tid + 256) >> 2,  ch1_kc = tid & 3;

    float acc[4][4][4];
#pragma unroll
    for (int mi = 0; mi < 4; mi++)
#pragma unroll
        for (int ni = 0; ni < 4; ni++)
#pragma unroll
            for (int c = 0; c < 4; c++) acc[mi][ni][c] = 0.f;

    const int NCH = Cc / 32;   // 40 stages

    // ldmatrix base addresses (R7-verified mapping)
    const uint32_t aRow = wm * 64 + (lane & 7) + ((lane >> 3) & 1) * 8;
    const uint32_t aOff = aRow * STRB + (lane >> 4) * 16;
    const uint32_t bRow = wn * 32 + (lane & 7) + ((lane >> 4) << 3);
    const uint32_t bOff = bRow * STRB + ((lane >> 3) & 1) * 16;

    auto issue_stage = [&](int stage, int buf) {
        const int kc0 = stage * 32;
        const uint32_t stB = sb + buf * STAGE_B;
        {
            uint32_t so = ch0_row * STRB + ch0_kc * 16;
            long ga = (long)(m0 + ch0_row) * Cc + kc0 + ch0_kc * 8;
            long gb = (long)(n0 + ch0_row) * Cc + kc0 + ch0_kc * 8;
            CP_ASYNC16(stB + OFF_A + so, A_g + ga);
            CP_ASYNC16(stB + OFF_B + so, W_g + gb);
        }
        {
            uint32_t so = ch1_row * STRB + ch1_kc * 16;
            long ga = (long)(m0 + ch1_row) * Cc + kc0 + ch1_kc * 8;
            long gb = (long)(n0 + ch1_row) * Cc + kc0 + ch1_kc * 8;
            CP_ASYNC16(stB + OFF_A + so, A_g + ga);
            CP_ASYNC16(stB + OFF_B + so, W_g + gb);
        }
        CP_COMMIT();
    };

    issue_stage(0, 0);
    issue_stage(1, 1);
    issue_stage(2, 2);

    for (int c = 0; c < NCH; c++) {
        // One commit per iteration keeps the group count exact.
        if (c + 3 < NCH) issue_stage(c + 3, (c + 3) & 3);
        else             CP_COMMIT();
        CP_WAIT(3);
        __syncthreads();

        const uint32_t base = sb + (c & 3) * STAGE_B;
#pragma unroll
        for (int kk = 0; kk < 2; kk++) {
            const uint32_t ko = kk * 32;
            uint32_t b[4][2];
#pragma unroll
            for (int p = 0; p < 2; p++) {
                uint32_t t0, t1, t2, t3;
                LDSM4(t0, t1, t2, t3, base + OFF_B + bOff + p * (16 * STRB) + ko);
                b[2 * p][0] = t0;     b[2 * p][1] = t1;
                b[2 * p + 1][0] = t2; b[2 * p + 1][1] = t3;
            }
#pragma unroll
            for (int mi = 0; mi < 4; mi++) {
                uint32_t a[4];
                LDSM4(a[0], a[1], a[2], a[3],
                      base + OFF_A + aOff + mi * (16 * STRB) + ko);
#pragma unroll
                for (int ni = 0; ni < 4; ni++)
                    F16_MMA(acc[mi][ni], a, b[ni]);
            }
        }
        __syncthreads();
    }

    // Epilogue (verified fragment mapping)
#pragma unroll
    for (int mi = 0; mi < 4; mi++) {
#pragma unroll
        for (int ni = 0; ni < 4; ni++) {
            int r_lo = m0 + wm * 64 + mi * 16 + gid;
            int cn = n0 + wn * 32 + ni * 8 + 2 * tig;
            float2 lo = make_float2(acc[mi][ni][0], acc[mi][ni][1]);
            float2 hi = make_float2(acc[mi][ni][2], acc[mi][ni][3]);
            if (mode == 0) {
                *(float2*)(O + (long)r_lo * Cc + cn)       = lo;
                *(float2*)(O + (long)(r_lo + 8) * Cc + cn) = hi;
            } else {
                int h_ = n0 >> 7;
                int d_ = cn - n0;
                int b0_ = r_lo >> 11, t0_ = r_lo & (Tt - 1);
                int b1_ = (r_lo + 8) >> 11, t1_ = (r_lo + 8) & (Tt - 1);
                long base0 = ((long)(b0_ * Hh + h_) * Tt + t0_) * Dd + d_;
                long base1 = ((long)(b1_ * Hh + h_) * Tt + t1_) * Dd + d_;
                *(float2*)(O + base0) = lo;
                *(float2*)(O + base1) = hi;
            }
        }
    }
}

// ---------------------------------------------------------------------------
// Fused RoPE + RMSNorm on g_q / g_k, one warp per (b,h,t) row of 128.
// ---------------------------------------------------------------------------
__global__ __launch_bounds__(256) void rope_rms_kernel(
    const float* __restrict__ cosp, const float* __restrict__ sinp)
{
    int warp = threadIdx.x >> 5;
    int lane = threadIdx.x & 31;
    int row = blockIdx.x * 8 + warp;
    float* buf = (blockIdx.y == 0) ? g_q : g_k;
    int t = row & (Tt - 1);
    float* p = buf + (long)row * Dd;

    float x0 = p[lane], x1 = p[lane + 32], x2 = p[lane + 64], x3 = p[lane + 96];
    float c0 = cosp[t * 64 + lane], c1 = cosp[t * 64 + lane + 32];
    float s0 = sinp[t * 64 + lane], s1 = sinp[t * 64 + lane + 32];

    float y0 =  x0 * c0 + x2 * s0;
    float y2 = -x0 * s0 + x2 * c0;
    float y1 =  x1 * c1 + x3 * s1;
    float y3 = -x1 * s1 + x3 * c1;

    float ss = y0 * y0 + y1 * y1 + y2 * y2 + y3 * y3;
#pragma unroll
    for (int o = 16; o; o >>= 1) ss += __shfl_xor_sync(0xFFFFFFFFu, ss, o);
    float inv = rsqrtf(ss * (1.0f / 128.0f) + 1e-5f);

    p[lane]      = y0 * inv;
    p[lane + 32] = y1 * inv;
    p[lane + 64] = y2 * inv;
    p[lane + 96] = y3 * inv;
}

// ---------------------------------------------------------------------------
// Flash attention, bf16 split-3 mma.sync (R5/R7-proven). Epilogue writes the
// attention output directly in fp16 for the proj GEMM.
// ---------------------------------------------------------------------------
#define FQP 68
#define FKP 68
#define FVP 36
#define FLASH_SMEM_BYTES ((2*128*FQP + 2*64*FKP + 2*128*FVP) * 4)

__global__ __launch_bounds__(256) void flash_mma_kernel()
{
    extern __shared__ uint32_t smu[];
    uint32_t* Qh = smu;
    uint32_t* Ql = Qh + 128 * FQP;
    uint32_t* Kh = Ql + 128 * FQP;
    uint32_t* Kl = Kh + 64 * FKP;
    uint32_t* Vh = Kl + 64 * FKP;
    uint32_t* Vl = Vh + 128 * FVP;

    const int tid  = threadIdx.x;
    const int wid  = tid >> 5;
    const int lane = tid & 31;
    const int gid  = lane >> 2;
    const int tig  = lane & 3;

    const int qtile = gridDim.x - 1 - blockIdx.x;
    const int bh = blockIdx.y;
    const int b_ = bh / Hh, h_ = bh % Hh;
    const long base = (long)bh * Tt * Dd;
    const float* qb = g_q + base;
    const float* kb = g_k + base;
    const float* vb = g_v + base;
    const int qb0 = qtile * 128;

    for (int i = tid; i < 128 * 32; i += 256) {
        int r = i >> 5, f4 = i & 31;
        float4 v = *(const float4*)(qb + (long)(qb0 + r) * Dd + f4 * 4);
        uint32_t h0, l0, h1, l1;
        cvt_split_pair(v.x * SOFT_SCALE, v.y * SOFT_SCALE, h0, l0);
        cvt_split_pair(v.z * SOFT_SCALE, v.w * SOFT_SCALE, h1, l1);
        Qh[r * FQP + 2 * f4]     = h0; Qh[r * FQP + 2 * f4 + 1] = h1;
        Ql[r * FQP + 2 * f4]     = l0; Ql[r * FQP + 2 * f4 + 1] = l1;
    }

    float o[16][4];
    float m_[2], l_[2];
#pragma unroll
    for (int ni = 0; ni < 16; ni++)
#pragma unroll
        for (int c = 0; c < 4; c++) o[ni][c] = 0.f;
    m_[0] = m_[1] = -1e30f;
    l_[0] = l_[1] = 0.f;

    const int qrow = wid * 16;
    const int ktmax = 2 * qtile + 2;

    for (int kt = 0; kt < ktmax; kt++) {
        __syncthreads();
        const int kbase = kt * 64;

        for (int i = tid; i < 64 * 32; i += 256) {
            int r = i >> 5, f4 = i & 31;
            float4 v = *(const float4*)(kb + (long)(kbase + r) * Dd + f4 * 4);
            uint32_t h0, l0, h1, l1;
            cvt_split_pair(v.x, v.y, h0, l0);
            cvt_split_pair(v.z, v.w, h1, l1);
            Kh[r * FKP + 2 * f4]     = h0; Kh[r * FKP + 2 * f4 + 1] = h1;
            Kl[r * FKP + 2 * f4]     = l0; Kl[r * FKP + 2 * f4 + 1] = l1;
        }
        for (int i = tid; i < 128 * 32; i += 256) {
            int d = i & 127, kp = i >> 7;
            float v0 = vb[(long)(kbase + 2 * kp) * Dd + d];
            float v1 = vb[(long)(kbase + 2 * kp + 1) * Dd + d];
            uint32_t h, l;
            cvt_split_pair(v0, v1, h, l);
            Vh[d * FVP + kp] = h;
            Vl[d * FVP + kp] = l;
        }
        __syncthreads();

        float s[8][4];
#pragma unroll
        for (int t = 0; t < 8; t++)
#pragma unroll
            for (int c = 0; c < 4; c++) s[t][c] = 0.f;

#pragma unroll
        for (int j = 0; j < 8; j++) {
            uint32_t ah[4], al[4];
            ah[0] = Qh[(qrow + gid) * FQP + 8 * j + tig];
            ah[1] = Qh[(qrow + gid + 8) * FQP + 8 * j + tig];
            ah[2] = Qh[(qrow + gid) * FQP + 8 * j + tig + 4];
            ah[3] = Qh[(qrow + gid + 8) * FQP + 8 * j + tig + 4];
            al[0] = Ql[(qrow + gid) * FQP + 8 * j + tig];
            al[1] = Ql[(qrow + gid + 8) * FQP + 8 * j + tig];
            al[2] = Ql[(qrow + gid) * FQP + 8 * j + tig + 4];
            al[3] = Ql[(qrow + gid + 8) * FQP + 8 * j + tig + 4];
#pragma unroll
            for (int ni = 0; ni < 8; ni++) {
                uint32_t bh2[2], bl2[2];
                bh2[0] = Kh[(8 * ni + gid) * FKP + 8 * j + tig];
                bh2[1] = Kh[(8 * ni + gid) * FKP + 8 * j + tig + 4];
                bl2[0] = Kl[(8 * ni + gid) * FKP + 8 * j + tig];
                bl2[1] = Kl[(8 * ni + gid) * FKP + 8 * j + tig + 4];
                BF16_MMA(s[ni], ah, bh2);
                BF16_MMA(s[ni], ah, bl2);
                BF16_MMA(s[ni], al, bh2);
            }
        }

        if (kt >= 2 * qtile) {
            int r0g = qb0 + qrow + gid;
#pragma unroll
            for (int t = 0; t < 8; t++) {
                int col = kbase + 8 * t + 2 * tig;
                if (col     > r0g)     s[t][0] = -1e30f;
                if (col + 1 > r0g)     s[t][1] = -1e30f;
                if (col     > r0g + 8) s[t][2] = -1e30f;
                if (col + 1 > r0g + 8) s[t][3] = -1e30f;
            }
        }

#pragma unroll
        for (int r = 0; r < 2; r++) {
            float mx = -1e30f;
#pragma unroll
            for (int t = 0; t < 8; t++)
                mx = fmaxf(mx, fmaxf(s[t][2 * r], s[t][2 * r + 1]));
            mx = fmaxf(mx, __shfl_xor_sync(0xFFFFFFFFu, mx, 1));
            mx = fmaxf(mx, __shfl_xor_sync(0xFFFFFFFFu, mx, 2));
            float mn = fmaxf(m_[r], mx);
            float alpha = __expf(m_[r] - mn);
            float sum = 0.f;
#pragma unroll
            for (int t = 0; t < 8; t++) {
                float p0 = __expf(s[t][2 * r]     - mn);
                float p1 = __expf(s[t][2 * r + 1] - mn);
                s[t][2 * r] = p0; s[t][2 * r + 1] = p1;
                sum += p0 + p1;
            }
            sum += __shfl_xor_sync(0xFFFFFFFFu, sum, 1);
            sum += __shfl_xor_sync(0xFFFFFFFFu, sum, 2);
            l_[r] = l_[r] * alpha + sum;
            m_[r] = mn;
#pragma unroll
            for (int ni = 0; ni < 16; ni++) {
                o[ni][2 * r]     *= alpha;
                o[ni][2 * r + 1] *= alpha;
            }
        }

#pragma unroll
        for (int j = 0; j < 4; j++) {
            uint32_t ah[4], al[4];
            cvt_split_pair(s[2 * j][0],     s[2 * j][1],     ah[0], al[0]);
            cvt_split_pair(s[2 * j][2],     s[2 * j][3],     ah[1], al[1]);
            cvt_split_pair(s[2 * j + 1][0], s[2 * j + 1][1], ah[2], al[2]);
            cvt_split_pair(s[2 * j + 1][2], s[2 * j + 1][3], ah[3], al[3]);
#pragma unroll
            for (int ni = 0; ni < 16; ni++) {
                uint32_t bh2[2], bl2[2];
                bh2[0] = Vh[(8 * ni + gid) * FVP + 8 * j + tig];
                bh2[1] = Vh[(8 * ni + gid) * FVP + 8 * j + tig + 4];
                bl2[0] = Vl[(8 * ni + gid) * FVP + 8 * j + tig];
                bl2[1] = Vl[(8 * ni + gid) * FVP + 8 * j + tig + 4];
                BF16_MMA(o[ni], ah, bh2);
                BF16_MMA(o[ni], ah, bl2);
                BF16_MMA(o[ni], al, bh2);
            }
        }
    }

    // Epilogue: normalize, convert to fp16, write g_atf directly.
    float inv0 = 1.f / l_[0];
    float inv1 = 1.f / l_[1];
    int r0g = qb0 + qrow + gid;
    long pb0 = (((long)(b_ * Tt + r0g))     * Cc + h_ * Dd) >> 1;
    long pb1 = (((long)(b_ * Tt + r0g + 8)) * Cc + h_ * Dd) >> 1;
#pragma unroll
    for (int ni = 0; ni < 16; ni++) {
        int dp = 4 * ni + tig;
        __half2 p0 = __floats2half2_rn(o[ni][0] * inv0, o[ni][1] * inv0);
        __half2 p1 = __floats2half2_rn(o[ni][2] * inv1, o[ni][3] * inv1);
        g_atf[pb0 + dp] = *reinterpret_cast<uint32_t*>(&p0);
        g_atf[pb1 + dp] = *reinterpret_cast<uint32_t*>(&p1);
    }
}

// ---------------------------------------------------------------------------
extern "C" void kernel_launch(void* const* d_in, const int* in_sizes, int n_in,
                              void* d_out, int out_size)
{
    const float* x    = (const float*)d_in[0];
    const float* cosp = (const float*)d_in[1];
    const float* sinp = (const float*)d_in[2];
    const float* Wq   = (const float*)d_in[3];
    const float* Wk   = (const float*)d_in[4];
    const float* Wv   = (const float*)d_in[5];
    const float* Wp   = (const float*)d_in[6];
    float* out = (float*)d_out;

    cudaFuncSetAttribute(gemm_f16,
                         cudaFuncAttributeMaxDynamicSharedMemorySize, GEMM_SMEM);
    cudaFuncSetAttribute(flash_mma_kernel,
                         cudaFuncAttributeMaxDynamicSharedMemorySize,
                         FLASH_SMEM_BYTES);

    uint32_t *xf_p, *wf_p, *atf_p;
    cudaGetSymbolAddress((void**)&xf_p, g_xf);
    cudaGetSymbolAddress((void**)&wf_p, g_wf);
    cudaGetSymbolAddress((void**)&atf_p, g_atf);

    // 0) Convert x and the four weight matrices to fp16
    const int xn4 = Mtot * Cc / 4;
    const int wn4 = WSZ / 4;
    cvt_f16_kernel<<<(xn4 + 255) / 256, 256>>>(x, xf_p, xn4);
    cvt_f16_kernel<<<(wn4 + 255) / 256, 256>>>(Wq, wf_p + 0 * WSZ / 2, wn4);
    cvt_f16_kernel<<<(wn4 + 255) / 256, 256>>>(Wk, wf_p + 1 * WSZ / 2, wn4);
    cvt_f16_kernel<<<(wn4 + 255) / 256, 256>>>(Wv, wf_p + 2 * WSZ / 2, wn4);
    cvt_f16_kernel<<<(wn4 + 255) / 256, 256>>>(Wp, wf_p + 3 * WSZ / 2, wn4);

    // 1) Q/K/V projections (fp16 single-pass, ldmatrix + 4-stage cp.async)
    gemm_f16<<<dim3(Cc / 128, Mtot / 128, 3), 256, GEMM_SMEM>>>(xf_p, nullptr, 1);
    // 2) RoPE + RMSNorm
    rope_rms_kernel<<<dim3((Bb * Hh * Tt) / 8, 2), 256>>>(cosp, sinp);
    // 3) Flash attention (bf16 split-3; writes fp16 attention output)
    flash_mma_kernel<<<dim3(Tt / 128, Bb * Hh), 256, FLASH_SMEM_BYTES>>>();
    // 4) Output projection (fp16 single-pass)
    gemm_f16<<<dim3(Cc / 128, Mtot / 128, 1), 256, GEMM_SMEM>>>(atf_p, out, 0);
}

// round 10
// speedup vs baseline: 2.4580x; 1.6504x over previous
#include <cuda_runtime.h>
#include <cuda_bf16.h>
#include <cuda_fp16.h>
#include <cstdint>

// Problem constants
#define Bb 2
#define Tt 2048
#define Cc 1280
#define Hh 10
#define Dd 128
#define Mtot (Bb*Tt)          // 4096
#define WSZ (Cc*Cc)
#define SOFT_SCALE 0.08838834764831845f  // 1/sqrt(128)

// Scratch (device globals; allocation-free rule)
__device__ float g_q[Bb*Hh*Tt*Dd];
__device__ float g_k[Bb*Hh*Tt*Dd];
__device__ float g_v[Bb*Hh*Tt*Dd];
__device__ uint32_t g_xf[Mtot*Cc/2];     // x in fp16 (half2 packed)
__device__ uint32_t g_wf[4*WSZ/2];       // Wq,Wk,Wv,Wproj in fp16
__device__ uint32_t g_atf[Mtot*Cc/2];    // attention out fp16 [b,t,h,d]
__device__ uint32_t g_qf[Bb*Hh*Tt*Dd/2]; // q fp16 pairs, pre-scaled, post rope+rms
__device__ uint32_t g_kf[Bb*Hh*Tt*Dd/2]; // k fp16 pairs, post rope+rms
__device__ uint32_t g_vt[Bb*Hh*Dd*Tt/2]; // v fp16, [bh][d][t-pair]

// ---------------------------------------------------------------------------
// Helpers
// ---------------------------------------------------------------------------
#define F16_MMA(d, a, b) \
    asm volatile( \
        "mma.sync.aligned.m16n8k16.row.col.f32.f16.f16.f32 " \
        "{%0,%1,%2,%3}, {%4,%5,%6,%7}, {%8,%9}, {%0,%1,%2,%3};\n" \
        : "+f"(d[0]), "+f"(d[1]), "+f"(d[2]), "+f"(d[3]) \
        : "r"(a[0]), "r"(a[1]), "r"(a[2]), "r"(a[3]), "r"(b[0]), "r"(b[1]))

#define LDSM4(r0, r1, r2, r3, addr) \
    asm volatile("ldmatrix.sync.aligned.m8n8.x4.shared.b16 {%0,%1,%2,%3}, [%4];" \
        : "=r"(r0), "=r"(r1), "=r"(r2), "=r"(r3) : "r"(addr))

#define CP_ASYNC16(dst, src) \
    asm volatile("cp.async.cg.shared.global [%0], [%1], 16;" \
        :: "r"(dst), "l"(src))
#define CP_COMMIT() asm volatile("cp.async.commit_group;" ::: "memory")
#define CP_WAIT(n)  asm volatile("cp.async.wait_group %0;" :: "n"(n) : "memory")

__device__ __forceinline__ uint32_t s2u(const void* p) {
    uint32_t a;
    asm("{ .reg .u64 t; cvta.to.shared.u64 t, %1; cvt.u32.u64 %0, t; }"
        : "=r"(a) : "l"(p));
    return a;
}

__device__ __forceinline__ uint32_t packh2(float x, float y) {
    __half2 p = __floats2half2_rn(x, y);
    return *reinterpret_cast<uint32_t*>(&p);
}

// ---------------------------------------------------------------------------
// Elementwise fp32 -> fp16 convert (GEMM operand pre-pass)
// ---------------------------------------------------------------------------
__global__ __launch_bounds__(256) void cvt_f16_kernel(
    const float* __restrict__ src, uint32_t* __restrict__ dst, int n4)
{
    int i = blockIdx.x * 256 + threadIdx.x;
    if (i >= n4) return;
    float4 v = *(const float4*)(src + 4 * (long)i);
    dst[2 * i]     = packh2(v.x, v.y);
    dst[2 * i + 1] = packh2(v.z, v.w);
}

// ---------------------------------------------------------------------------
// fp16 single-pass GEMM (R8-verified): Out[m,n] = sum_k A[m,k] * W[n,k]
// ---------------------------------------------------------------------------
#define STRB 80
#define OFF_A 0
#define OFF_B (128*STRB)
#define STAGE_B (2*128*STRB)      // 20480
#define GEMM_SMEM (4*STAGE_B)     // 81920

__global__ __launch_bounds__(256, 2) void gemm_f16(
    const uint32_t* __restrict__ A_u,
    float* __restrict__ Out,
    int mode)
{
    extern __shared__ char smc[];
    const uint32_t sb = s2u(smc);

    const int tid  = threadIdx.x;
    const int warp = tid >> 5;
    const int lane = tid & 31;
    const int wm = warp & 1;
    const int wn = warp >> 1;
    const int gid = lane >> 2;
    const int tig = lane & 3;

    const int m0 = blockIdx.y * 128;
    const int n0 = blockIdx.x * 128;
    const int z  = (mode == 0) ? 3 : blockIdx.z;

    const __half* A_g = (const __half*)A_u;
    const __half* W_g = (const __half*)(g_wf) + (long)z * WSZ;
    float* O = (mode == 0) ? Out : ((z == 0) ? g_q : ((z == 1) ? g_k : g_v));

    const int ch0_row = tid >> 2,          ch0_kc = tid & 3;
    const int ch1_row = (tid + 256) >> 2,  ch1_kc = tid & 3;

    float acc[4][4][4];
#pragma unroll
    for (int mi = 0; mi < 4; mi++)
#pragma unroll
        for (int ni = 0; ni < 4; ni++)
#pragma unroll
            for (int c = 0; c < 4; c++) acc[mi][ni][c] = 0.f;

    const int NCH = Cc / 32;   // 40

    const uint32_t aRow = wm * 64 + (lane & 7) + ((lane >> 3) & 1) * 8;
    const uint32_t aOff = aRow * STRB + (lane >> 4) * 16;
    const uint32_t bRow = wn * 32 + (lane & 7) + ((lane >> 4) << 3);
    const uint32_t bOff = bRow * STRB + ((lane >> 3) & 1) * 16;

    auto issue_stage = [&](int stage, int buf) {
        const int kc0 = stage * 32;
        const uint32_t stB = sb + buf * STAGE_B;
        {
            uint32_t so = ch0_row * STRB + ch0_kc * 16;
            long ga = (long)(m0 + ch0_row) * Cc + kc0 + ch0_kc * 8;
            long gb = (long)(n0 + ch0_row) * Cc + kc0 + ch0_kc * 8;
            CP_ASYNC16(stB + OFF_A + so, A_g + ga);
            CP_ASYNC16(stB + OFF_B + so, W_g + gb);
        }
        {
            uint32_t so = ch1_row * STRB + ch1_kc * 16;
            long ga = (long)(m0 + ch1_row) * Cc + kc0 + ch1_kc * 8;
            long gb = (long)(n0 + ch1_row) * Cc + kc0 + ch1_kc * 8;
            CP_ASYNC16(stB + OFF_A + so, A_g + ga);
            CP_ASYNC16(stB + OFF_B + so, W_g + gb);
        }
        CP_COMMIT();
    };

    issue_stage(0, 0);
    issue_stage(1, 1);
    issue_stage(2, 2);

    for (int c = 0; c < NCH; c++) {
        if (c + 3 < NCH) issue_stage(c + 3, (c + 3) & 3);
        else             CP_COMMIT();
        CP_WAIT(3);
        __syncthreads();

        const uint32_t base = sb + (c & 3) * STAGE_B;
#pragma unroll
        for (int kk = 0; kk < 2; kk++) {
            const uint32_t ko = kk * 32;
            uint32_t b[4][2];
#pragma unroll
            for (int p = 0; p < 2; p++) {
                uint32_t t0, t1, t2, t3;
                LDSM4(t0, t1, t2, t3, base + OFF_B + bOff + p * (16 * STRB) + ko);
                b[2 * p][0] = t0;     b[2 * p][1] = t1;
                b[2 * p + 1][0] = t2; b[2 * p + 1][1] = t3;
            }
#pragma unroll
            for (int mi = 0; mi < 4; mi++) {
                uint32_t a[4];
                LDSM4(a[0], a[1], a[2], a[3],
                      base + OFF_A + aOff + mi * (16 * STRB) + ko);
#pragma unroll
                for (int ni = 0; ni < 4; ni++)
                    F16_MMA(acc[mi][ni], a, b[ni]);
            }
        }
        __syncthreads();
    }

#pragma unroll
    for (int mi = 0; mi < 4; mi++) {
#pragma unroll
        for (int ni = 0; ni < 4; ni++) {
            int r_lo = m0 + wm * 64 + mi * 16 + gid;
            int cn = n0 + wn * 32 + ni * 8 + 2 * tig;
            float2 lo = make_float2(acc[mi][ni][0], acc[mi][ni][1]);
            float2 hi = make_float2(acc[mi][ni][2], acc[mi][ni][3]);
            if (mode == 0) {
                *(float2*)(O + (long)r_lo * Cc + cn)       = lo;
                *(float2*)(O + (long)(r_lo + 8) * Cc + cn) = hi;
            } else {
                int h_ = n0 >> 7;
                int d_ = cn - n0;
                int b0_ = r_lo >> 11, t0_ = r_lo & (Tt - 1);
                int b1_ = (r_lo + 8) >> 11, t1_ = (r_lo + 8) & (Tt - 1);
                long base0 = ((long)(b0_ * Hh + h_) * Tt + t0_) * Dd + d_;
                long base1 = ((long)(b1_ * Hh + h_) * Tt + t1_) * Dd + d_;
                *(float2*)(O + base0) = lo;
                *(float2*)(O + base1) = hi;
            }
        }
    }
}

// ---------------------------------------------------------------------------
// Fused RoPE + RMSNorm; reads f32 g_q/g_k, writes packed fp16 g_qf/g_kf.
// Lane owns d = {2l, 2l+1, 2l+64, 2l+65}; pair p covers d = (2p, 2p+1).
// Q output is pre-scaled by 1/sqrt(D).
// ---------------------------------------------------------------------------
__global__ __launch_bounds__(256) void rope_rms_f16_kernel(
    const float* __restrict__ cosp, const float* __restrict__ sinp)
{
    int warp = threadIdx.x >> 5;
    int lane = threadIdx.x & 31;
    int row = blockIdx.x * 8 + warp;          // 0 .. B*H*T-1
    const float* src = (blockIdx.y == 0) ? g_q : g_k;
    uint32_t* dst = (blockIdx.y == 0) ? g_qf : g_kf;
    int t = row & (Tt - 1);

    const float* p = src + (long)row * Dd;
    float2 a01 = *(const float2*)(p + 2 * lane);
    float2 a23 = *(const float2*)(p + 64 + 2 * lane);
    float2 cc = *(const float2*)(cosp + t * 64 + 2 * lane);
    float2 ss2 = *(const float2*)(sinp + t * 64 + 2 * lane);

    float y0 =  a01.x * cc.x + a23.x * ss2.x;
    float y2 = -a01.x * ss2.x + a23.x * cc.x;
    float y1 =  a01.y * cc.y + a23.y * ss2.y;
    float y3 = -a01.y * ss2.y + a23.y * cc.y;

    float ss = y0 * y0 + y1 * y1 + y2 * y2 + y3 * y3;
#pragma unroll
    for (int o = 16; o; o >>= 1) ss += __shfl_xor_sync(0xFFFFFFFFu, ss, o);
    float inv = rsqrtf(ss * (1.0f / 128.0f) + 1e-5f);
    if (blockIdx.y == 0) inv *= SOFT_SCALE;

    dst[(long)row * 64 + lane]      = packh2(y0 * inv, y1 * inv);
    dst[(long)row * 64 + 32 + lane] = packh2(y2 * inv, y3 * inv);
}

// ---------------------------------------------------------------------------
// V pack/transpose: f32 [bh][t][d] -> fp16 pairs [bh][d][t/2].
// ---------------------------------------------------------------------------
__global__ __launch_bounds__(256) void vpack_kernel()
{
    __shared__ float sv[64][129];
    const int tid = threadIdx.x;
    const int bh = blockIdx.y;
    const int t0 = blockIdx.x * 64;
    const float* vsrc = g_v + (long)bh * Tt * Dd;

    for (int idx = tid; idx < 64 * 32; idx += 256) {
        int tr = idx >> 5, c4 = (idx & 31) << 2;
        float4 v = *(const float4*)(vsrc + (long)(t0 + tr) * Dd + c4);
        sv[tr][c4] = v.x; sv[tr][c4 + 1] = v.y;
        sv[tr][c4 + 2] = v.z; sv[tr][c4 + 3] = v.w;
    }
    __syncthreads();

    uint32_t* vdst = g_vt + (long)bh * Dd * (Tt / 2) + (t0 >> 1);
    for (int idx = tid; idx < 128 * 32; idx += 256) {
        int d = idx >> 5, tp = idx & 31;
        vdst[(long)d * (Tt / 2) + tp] = packh2(sv[2 * tp][d], sv[2 * tp + 1][d]);
    }
}

// ---------------------------------------------------------------------------
// Flash attention, fp16 single mma.sync. Br=128, Bc=64, 8 warps (16 q-rows
// each). Operands pre-converted; tile loads are raw 16B copies.
// ---------------------------------------------------------------------------
#define FQP 68   // Q/K pair stride
#define FVP 36   // Vt pair stride
#define FLASH_SMEM_BYTES ((128*FQP + 64*FQP + 128*FVP) * 4)   // 70,656

__global__ __launch_bounds__(256, 2) void flash_f16_kernel()
{
    extern __shared__ uint32_t smu[];
    uint32_t* Qf = smu;                  // [128][68]
    uint32_t* Kf = Qf + 128 * FQP;       // [64][68]
    uint32_t* Vt = Kf + 64 * FQP;        // [128][36]

    const int tid  = threadIdx.x;
    const int wid  = tid >> 5;
    const int lane = tid & 31;
    const int gid  = lane >> 2;
    const int tig  = lane & 3;

    const int qtile = gridDim.x - 1 - blockIdx.x;   // heavy tiles first
    const int bh = blockIdx.y;
    const int b_ = bh / Hh, h_ = bh % Hh;
    const uint32_t* qsrc = g_qf + (long)bh * Tt * 64;
    const uint32_t* ksrc = g_kf + (long)bh * Tt * 64;
    const uint32_t* vsrc = g_vt + (long)bh * Dd * (Tt / 2);
    const int qb0 = qtile * 128;

    // Q tile: 128 rows x 16 uint4 chunks
    for (int idx = tid; idx < 2048; idx += 256) {
        int r = idx >> 4, c = (idx & 15) << 2;
        uint4 v = *(const uint4*)(qsrc + (long)(qb0 + r) * 64 + c);
        *(uint4*)(Qf + r * FQP + c) = v;
    }

    float o[16][4];
    float m_[2], l_[2];
#pragma unroll
    for (int ni = 0; ni < 16; ni++)
#pragma unroll
        for (int c = 0; c < 4; c++) o[ni][c] = 0.f;
    m_[0] = m_[1] = -1e30f;
    l_[0] = l_[1] = 0.f;

    const int qrow = wid * 16;
    const int ktmax = 2 * qtile + 2;

    for (int kt = 0; kt < ktmax; kt++) {
        __syncthreads();
        const int kbase = kt * 64;

        // K tile: 64 rows x 16 uint4 chunks  (R9 bug fixed: >>4 / &15)
        for (int idx = tid; idx < 1024; idx += 256) {
            int r = idx >> 4, c = (idx & 15) << 2;
            uint4 v = *(const uint4*)(ksrc + (long)(kbase + r) * 64 + c);
            *(uint4*)(Kf + r * FQP + c) = v;
        }
        // V tile: 128 d-rows x 8 uint4 chunks
        for (int idx = tid; idx < 1024; idx += 256) {
            int d = idx >> 3, c = (idx & 7) << 2;
            uint4 v = *(const uint4*)(vsrc + (long)d * (Tt / 2) + (kbase >> 1) + c);
            *(uint4*)(Vt + d * FVP + c) = v;
        }
        __syncthreads();

        // ---- S = Q K^T ----
        float s[8][4];
#pragma unroll
        for (int t = 0; t < 8; t++)
#pragma unroll
            for (int c = 0; c < 4; c++) s[t][c] = 0.f;

#pragma unroll
        for (int j = 0; j < 8; j++) {
            uint32_t a[4];
            a[0] = Qf[(qrow + gid) * FQP + 8 * j + tig];
            a[1] = Qf[(qrow + gid + 8) * FQP + 8 * j + tig];
            a[2] = Qf[(qrow + gid) * FQP + 8 * j + tig + 4];
            a[3] = Qf[(qrow + gid + 8) * FQP + 8 * j + tig + 4];
#pragma unroll
            for (int ni = 0; ni < 8; ni++) {
                uint32_t b[2];
                b[0] = Kf[(8 * ni + gid) * FQP + 8 * j + tig];
                b[1] = Kf[(8 * ni + gid) * FQP + 8 * j + tig + 4];
                F16_MMA(s[ni], a, b);
            }
        }

        // ---- causal mask ----
        if (kt >= 2 * qtile) {
            int r0g = qb0 + qrow + gid;
#pragma unroll
            for (int t = 0; t < 8; t++) {
                int col = kbase + 8 * t + 2 * tig;
                if (col     > r0g)     s[t][0] = -1e30f;
                if (col + 1 > r0g)     s[t][1] = -1e30f;
                if (col     > r0g + 8) s[t][2] = -1e30f;
                if (col + 1 > r0g + 8) s[t][3] = -1e30f;
            }
        }

        // ---- online softmax ----
#pragma unroll
        for (int r = 0; r < 2; r++) {
            float mx = -1e30f;
#pragma unroll
            for (int t = 0; t < 8; t++)
                mx = fmaxf(mx, fmaxf(s[t][2 * r], s[t][2 * r + 1]));
            mx = fmaxf(mx, __shfl_xor_sync(0xFFFFFFFFu, mx, 1));
            mx = fmaxf(mx, __shfl_xor_sync(0xFFFFFFFFu, mx, 2));
            float mn = fmaxf(m_[r], mx);
            float alpha = __expf(m_[r] - mn);
            float sum = 0.f;
#pragma unroll
            for (int t = 0; t < 8; t++) {
                float p0 = __expf(s[t][2 * r]     - mn);
                float p1 = __expf(s[t][2 * r + 1] - mn);
                s[t][2 * r] = p0; s[t][2 * r + 1] = p1;
                sum += p0 + p1;
            }
            sum += __shfl_xor_sync(0xFFFFFFFFu, sum, 1);
            sum += __shfl_xor_sync(0xFFFFFFFFu, sum, 2);
            l_[r] = l_[r] * alpha + sum;
            m_[r] = mn;
#pragma unroll
            for (int ni = 0; ni < 16; ni++) {
                o[ni][2 * r]     *= alpha;
                o[ni][2 * r + 1] *= alpha;
            }
        }

        // ---- O += P V ----
#pragma unroll
        for (int j = 0; j < 4; j++) {
            uint32_t a[4];
            a[0] = packh2(s[2 * j][0],     s[2 * j][1]);
            a[1] = packh2(s[2 * j][2],     s[2 * j][3]);
            a[2] = packh2(s[2 * j + 1][0], s[2 * j + 1][1]);
            a[3] = packh2(s[2 * j + 1][2], s[2 * j + 1][3]);
#pragma unroll
            for (int ni = 0; ni < 16; ni++) {
                uint32_t b[2];
                b[0] = Vt[(8 * ni + gid) * FVP + 8 * j + tig];
                b[1] = Vt[(8 * ni + gid) * FVP + 8 * j + tig + 4];
                F16_MMA(o[ni], a, b);
            }
        }
    }

    // ---- epilogue: normalize, write fp16 g_atf [b,t,h,d] ----
    float inv0 = 1.f / l_[0];
    float inv1 = 1.f / l_[1];
    int r0g = qb0 + qrow + gid;
    long pb0 = (((long)(b_ * Tt + r0g))     * Cc + h_ * Dd) >> 1;
    long pb1 = (((long)(b_ * Tt + r0g + 8)) * Cc + h_ * Dd) >> 1;
#pragma unroll
    for (int ni = 0; ni < 16; ni++) {
        int dp = 4 * ni + tig;
        g_atf[pb0 + dp] = packh2(o[ni][0] * inv0, o[ni][1] * inv0);
        g_atf[pb1 + dp] = packh2(o[ni][2] * inv1, o[ni][3] * inv1);
    }
}

// ---------------------------------------------------------------------------
extern "C" void kernel_launch(void* const* d_in, const int* in_sizes, int n_in,
                              void* d_out, int out_size)
{
    const float* x    = (const float*)d_in[0];
    const float* cosp = (const float*)d_in[1];
    const float* sinp = (const float*)d_in[2];
    const float* Wq   = (const float*)d_in[3];
    const float* Wk   = (const float*)d_in[4];
    const float* Wv   = (const float*)d_in[5];
    const float* Wp   = (const float*)d_in[6];
    float* out = (float*)d_out;

    cudaFuncSetAttribute(gemm_f16,
                         cudaFuncAttributeMaxDynamicSharedMemorySize, GEMM_SMEM);
    cudaFuncSetAttribute(flash_f16_kernel,
                         cudaFuncAttributeMaxDynamicSharedMemorySize,
                         FLASH_SMEM_BYTES);

    uint32_t *xf_p, *wf_p, *atf_p;
    cudaGetSymbolAddress((void**)&xf_p, g_xf);
    cudaGetSymbolAddress((void**)&wf_p, g_wf);
    cudaGetSymbolAddress((void**)&atf_p, g_atf);

    // 0) Convert x and weights to fp16
    const int xn4 = Mtot * Cc / 4;
    const int wn4 = WSZ / 4;
    cvt_f16_kernel<<<(xn4 + 255) / 256, 256>>>(x, xf_p, xn4);
    cvt_f16_kernel<<<(wn4 + 255) / 256, 256>>>(Wq, wf_p + 0 * WSZ / 2, wn4);
    cvt_f16_kernel<<<(wn4 + 255) / 256, 256>>>(Wk, wf_p + 1 * WSZ / 2, wn4);
    cvt_f16_kernel<<<(wn4 + 255) / 256, 256>>>(Wv, wf_p + 2 * WSZ / 2, wn4);
    cvt_f16_kernel<<<(wn4 + 255) / 256, 256>>>(Wp, wf_p + 3 * WSZ / 2, wn4);

    // 1) Q/K/V projections (fp16, cp.async 4-stage)
    gemm_f16<<<dim3(Cc / 128, Mtot / 128, 3), 256, GEMM_SMEM>>>(xf_p, nullptr, 1);
    // 2) RoPE + RMSNorm -> packed fp16 q (pre-scaled), k
    rope_rms_f16_kernel<<<dim3((Bb * Hh * Tt) / 8, 2), 256>>>(cosp, sinp);
    // 2b) V pack/transpose -> fp16 d-major pairs
    vpack_kernel<<<dim3(Tt / 64, Bb * Hh), 256>>>();
    // 3) Flash attention (fp16 single mma)
    flash_f16_kernel<<<dim3(Tt / 128, Bb * Hh), 256, FLASH_SMEM_BYTES>>>();
    // 4) Output projection
    gemm_f16<<<dim3(Cc / 128, Mtot / 128, 1), 256, GEMM_SMEM>>>(atf_p, out, 0);
}